// round 12
// baseline (speedup 1.0000x reference)
#include <cuda_runtime.h>
#include <cuda_bf16.h>
#include <cstdint>

#define NN 50000
#define NE 640000
#define DD 128
#define NCLS 64
#define NB 49          // scan blocks: 49*1024 = 50176 >= NN

// ---------------- scratch (device globals) ----------------
__device__ uint4  g_Ah[(size_t)NN * 16];   // [NN][128] bf16 hi (head input)
__device__ uint4  g_Al[(size_t)NN * 16];   // [NN][128] bf16 lo
__device__ float4 g_bufB[(size_t)NN * 32]; // [NN][128] f32 (h1 scaled by dinv)
__device__ uint4  g_W1h[128 * 16], g_W1l[128 * 16];  // W1^T [n][k] bf16
__device__ uint4  g_W2h[128 * 16], g_W2l[128 * 16];
__device__ uint4  g_W3h[64 * 16],  g_W3l[64 * 16];
__device__ int4   g_cnt4[NB * 256];        // 50176 counters
__device__ int    g_bsum[NB];
__device__ int    g_bscan[NB];
__device__ int    g_off[NN + 1];
__device__ int    g_cur[NN];
__device__ float  g_dinv[NN];
__device__ int    g_col[NE];
__device__ int4   g_src4[NE / 4];
__device__ int4   g_dst4[NE / 4];

// ---------------- helpers ----------------
__device__ __forceinline__ uint32_t smem_u32(const void* p) {
    uint32_t a;
    asm("{ .reg .u64 t; cvta.to.shared.u64 t, %1; cvt.u32.u64 %0, t; }" : "=r"(a) : "l"(p));
    return a;
}
__device__ __forceinline__ void ldsm_x4(uint32_t& r0, uint32_t& r1, uint32_t& r2, uint32_t& r3,
                                        uint32_t addr) {
    asm volatile("ldmatrix.sync.aligned.m8n8.x4.shared.b16 {%0,%1,%2,%3}, [%4];"
                 : "=r"(r0), "=r"(r1), "=r"(r2), "=r"(r3) : "r"(addr));
}
__device__ __forceinline__ void mma_bf16(float* c, uint32_t a0, uint32_t a1, uint32_t a2,
                                         uint32_t a3, uint32_t b0, uint32_t b1) {
    asm volatile(
        "mma.sync.aligned.m16n8k16.row.col.f32.bf16.bf16.f32 "
        "{%0,%1,%2,%3}, {%4,%5,%6,%7}, {%8,%9}, {%0,%1,%2,%3};"
        : "+f"(c[0]), "+f"(c[1]), "+f"(c[2]), "+f"(c[3])
        : "r"(a0), "r"(a1), "r"(a2), "r"(a3), "r"(b0), "r"(b1));
}
__device__ __forceinline__ int warp_iscan(int v, int lane) {
    #pragma unroll
    for (int d = 1; d < 32; d <<= 1) {
        int t = __shfl_up_sync(0xffffffffu, v, d);
        if (lane >= d) v += t;
    }
    return v;
}
__device__ __forceinline__ uint32_t pack_hi(float a, float b, float& ra, float& rb) {
    __nv_bfloat16 ha = __float2bfloat16(a), hb = __float2bfloat16(b);
    ra = a - __bfloat162float(ha);
    rb = b - __bfloat162float(hb);
    return ((uint32_t)__bfloat16_as_ushort(hb) << 16) | __bfloat16_as_ushort(ha);
}
__device__ __forceinline__ uint32_t pack_lo(float ra, float rb) {
    return ((uint32_t)__bfloat16_as_ushort(__float2bfloat16(rb)) << 16) |
           __bfloat16_as_ushort(__float2bfloat16(ra));
}

// ---------------- CSR build ----------------
__global__ void zero_cnt_kernel() {
    int i = blockIdx.x * blockDim.x + threadIdx.x;
    if (i < NB * 256) g_cnt4[i] = make_int4(0, 0, 0, 0);
}

// fused dtype-detect + normalize + histogram, 4 edges/thread
__global__ void edges_kernel(const unsigned int* __restrict__ raw) {
    __shared__ int s_is64;
    if (threadIdx.x < 32) {
        size_t k = (size_t)threadIdx.x * (NE / 32);
        unsigned int hi = raw[2 * k + 1];
        unsigned int any = __ballot_sync(0xffffffffu, hi != 0u);
        if (threadIdx.x == 0) s_is64 = (any == 0u);
    }
    __syncthreads();
    int is64 = s_is64;
    int t = blockIdx.x * blockDim.x + threadIdx.x;
    if (t >= NE / 4) return;
    const uint4* raw4 = (const uint4*)raw;
    int4 s, d;
    if (is64) {
        uint4 a = raw4[2 * (size_t)t],            b = raw4[2 * (size_t)t + 1];
        uint4 c = raw4[(size_t)NE / 2 + 2 * t],   e = raw4[(size_t)NE / 2 + 2 * t + 1];
        s = make_int4((int)a.x, (int)a.z, (int)b.x, (int)b.z);
        d = make_int4((int)c.x, (int)c.z, (int)e.x, (int)e.z);
    } else {
        uint4 a = raw4[t], c = raw4[NE / 4 + t];
        s = make_int4((int)a.x, (int)a.y, (int)a.z, (int)a.w);
        d = make_int4((int)c.x, (int)c.y, (int)c.z, (int)c.w);
    }
    s.x = min(max(s.x, 0), NN - 1); s.y = min(max(s.y, 0), NN - 1);
    s.z = min(max(s.z, 0), NN - 1); s.w = min(max(s.w, 0), NN - 1);
    d.x = min(max(d.x, 0), NN - 1); d.y = min(max(d.y, 0), NN - 1);
    d.z = min(max(d.z, 0), NN - 1); d.w = min(max(d.w, 0), NN - 1);
    g_src4[t] = s;
    g_dst4[t] = d;
    int* cnt = (int*)g_cnt4;
    atomicAdd(&cnt[d.x], 1); atomicAdd(&cnt[d.y], 1);
    atomicAdd(&cnt[d.z], 1); atomicAdd(&cnt[d.w], 1);
}

// ---- multi-block scan (verified R10) ----
__global__ void scan1_kernel() {
    __shared__ int wsum[8];
    int t = threadIdx.x, b = blockIdx.x;
    int lane = t & 31, w = t >> 5;
    int4 v = g_cnt4[b * 256 + t];
    int s = v.x + v.y + v.z + v.w;
    int inc = warp_iscan(s, lane);
    if (lane == 31) wsum[w] = inc;
    __syncthreads();
    if (t == 0) {
        int tot = 0;
        #pragma unroll
        for (int i = 0; i < 8; ++i) tot += wsum[i];
        g_bsum[b] = tot;
    }
}

__global__ void scan2_kernel() {
    __shared__ int w0tot;
    int t = threadIdx.x, lane = t & 31, w = t >> 5;
    int s = (t < NB) ? g_bsum[t] : 0;
    int inc = warp_iscan(s, lane);
    if (w == 0 && lane == 31) w0tot = inc;
    __syncthreads();
    int excl = inc - s + (w ? w0tot : 0);
    if (t < NB) g_bscan[t] = excl;
    if (t == NB - 1) g_off[NN] = excl + s;
}

__global__ void scan3_kernel() {
    __shared__ int wsum[8];
    int t = threadIdx.x, b = blockIdx.x;
    int lane = t & 31, w = t >> 5;
    int4 v = g_cnt4[b * 256 + t];
    int s = v.x + v.y + v.z + v.w;
    int inc = warp_iscan(s, lane);
    if (lane == 31) wsum[w] = inc;
    __syncthreads();
    int woff = 0;
    #pragma unroll
    for (int i = 0; i < 8; ++i) if (i < w) woff += wsum[i];
    int excl = g_bscan[b] + woff + inc - s;
    int i0 = (b * 256 + t) * 4;
    int e0 = excl, e1 = e0 + v.x, e2 = e1 + v.y, e3 = e2 + v.z;
    if (i0 + 0 < NN) { g_off[i0 + 0] = e0; g_cur[i0 + 0] = e0; g_dinv[i0 + 0] = rsqrtf((float)(v.x + 1)); }
    if (i0 + 1 < NN) { g_off[i0 + 1] = e1; g_cur[i0 + 1] = e1; g_dinv[i0 + 1] = rsqrtf((float)(v.y + 1)); }
    if (i0 + 2 < NN) { g_off[i0 + 2] = e2; g_cur[i0 + 2] = e2; g_dinv[i0 + 2] = rsqrtf((float)(v.z + 1)); }
    if (i0 + 3 < NN) { g_off[i0 + 3] = e3; g_cur[i0 + 3] = e3; g_dinv[i0 + 3] = rsqrtf((float)(v.w + 1)); }
}

__global__ void fill_kernel() {
    int t = blockIdx.x * blockDim.x + threadIdx.x;
    if (t >= NE / 4) return;
    int4 s = g_src4[t], d = g_dst4[t];
    int p;
    p = atomicAdd(&g_cur[d.x], 1); g_col[p] = s.x;
    p = atomicAdd(&g_cur[d.y], 1); g_col[p] = s.y;
    p = atomicAdd(&g_cur[d.z], 1); g_col[p] = s.z;
    p = atomicAdd(&g_cur[d.w], 1); g_col[p] = s.w;
}

// ---------------- weight split ----------------
__global__ void split_w_kernel(const float* __restrict__ W1, const float* __restrict__ W2,
                               const float* __restrict__ W3) {
    int i = blockIdx.x * blockDim.x + threadIdx.x;
    float v; __nv_bfloat16* dh; __nv_bfloat16* dl; int n, k;
    if (i < 16384) {
        v = W1[i]; k = i >> 7; n = i & 127;
        dh = (__nv_bfloat16*)g_W1h; dl = (__nv_bfloat16*)g_W1l;
    } else if (i < 32768) {
        int j = i - 16384;
        v = W2[j]; k = j >> 7; n = j & 127;
        dh = (__nv_bfloat16*)g_W2h; dl = (__nv_bfloat16*)g_W2l;
    } else if (i < 40960) {
        int j = i - 32768;
        v = W3[j]; k = j >> 6; n = j & 63;
        dh = (__nv_bfloat16*)g_W3h; dl = (__nv_bfloat16*)g_W3l;
    } else return;
    __nv_bfloat16 h = __float2bfloat16(v);
    __nv_bfloat16 l = __float2bfloat16(v - __bfloat162float(h));
    dh[n * 128 + k] = h;
    dl[n * 128 + k] = l;
}

// ---------------- fused propagate + HMMA GEMM ----------------
// Gather (warp-per-node, 16 nodes/warp) -> bf16 hi/lo directly into MMA-swizzled
// smem -> 3-term HMMA with chunk-staged B. Persistent over tiles.
// SCALED_IN: input rows are pre-scaled by dinv (no per-edge dinv gather).
// OUT: 0 = f32 g_bufB scaled by dinv[row] (feeds F2), 1 = bf16 split g_Ah/g_Al.
template<bool SCALED_IN, int OUT, int LAY>
__global__ void __launch_bounds__(256, 2) prop_gemm(const float* __restrict__ xin,
                                                    const float* __restrict__ bias) {
    extern __shared__ uint4 smem4[];
    // layout (uint4 units): sAh[0..2047] sAl[2048..4095] sBh[4096..4607] sBl[4608..5119]
    const uint4* Wh = (LAY == 1) ? g_W1h : g_W2h;
    const uint4* Wl_ = (LAY == 1) ? g_W1l : g_W2l;

    int tid = threadIdx.x;
    int wid = tid >> 5;
    int lid = tid & 31;

    uint32_t sA_b  = smem_u32(smem4);
    uint32_t sAl_b = sA_b + 32768;
    uint32_t sBh_b = sA_b + 65536;
    uint32_t sBl_b = sA_b + 73728;

    // ldmatrix lane constants (verified R8)
    uint32_t a_row  = lid & 15;
    uint32_t a_half = lid >> 4;
    uint32_t a_x    = (a_row >> 1) & 3;
    uint32_t a_base = (wid * 16 + a_row) * 64;
    uint32_t b_c    = (lid & 7) + ((lid >> 4) & 1) * 8;
    uint32_t b_half = (lid >> 3) & 1;
    uint32_t b_x    = (b_c >> 1) & 3;
    uint32_t b_base = b_c * 64;

    const float4* X4 = SCALED_IN ? (const float4*)g_bufB : (const float4*)xin;

    for (int tile = blockIdx.x; tile < (NN + 127) / 128; tile += gridDim.x) {
        int m0 = tile * 128;

        // ---- gather phase: warp w handles rows w*16 .. w*16+15 ----
        for (int j = 0; j < 16; ++j) {
            int r = wid * 16 + j;
            int i = m0 + r;
            float ax = 0.f, ay = 0.f, az = 0.f, aw = 0.f;
            if (i < NN) {
                float di = g_dinv[i];
                float4 v = X4[(size_t)i * 32 + lid];
                if (SCALED_IN) { ax = v.x; ay = v.y; az = v.z; aw = v.w; }
                else { ax = di * v.x; ay = di * v.y; az = di * v.z; aw = di * v.w; }
                int e  = g_off[i];
                int e1 = g_off[i + 1];
                for (; e + 4 <= e1; e += 4) {
                    int s0 = g_col[e + 0], s1 = g_col[e + 1];
                    int s2 = g_col[e + 2], s3 = g_col[e + 3];
                    float4 v0 = X4[(size_t)s0 * 32 + lid];
                    float4 v1 = X4[(size_t)s1 * 32 + lid];
                    float4 v2 = X4[(size_t)s2 * 32 + lid];
                    float4 v3 = X4[(size_t)s3 * 32 + lid];
                    if (SCALED_IN) {
                        ax += v0.x + v1.x + v2.x + v3.x;
                        ay += v0.y + v1.y + v2.y + v3.y;
                        az += v0.z + v1.z + v2.z + v3.z;
                        aw += v0.w + v1.w + v2.w + v3.w;
                    } else {
                        float w0 = g_dinv[s0], w1 = g_dinv[s1];
                        float w2 = g_dinv[s2], w3 = g_dinv[s3];
                        ax += w0 * v0.x + w1 * v1.x + w2 * v2.x + w3 * v3.x;
                        ay += w0 * v0.y + w1 * v1.y + w2 * v2.y + w3 * v3.y;
                        az += w0 * v0.z + w1 * v1.z + w2 * v2.z + w3 * v3.z;
                        aw += w0 * v0.w + w1 * v1.w + w2 * v2.w + w3 * v3.w;
                    }
                }
                for (; e < e1; ++e) {
                    int s = g_col[e];
                    float4 vv = X4[(size_t)s * 32 + lid];
                    if (SCALED_IN) { ax += vv.x; ay += vv.y; az += vv.z; aw += vv.w; }
                    else {
                        float w = g_dinv[s];
                        ax += w * vv.x; ay += w * vv.y; az += w * vv.z; aw += w * vv.w;
                    }
                }
                ax *= di; ay *= di; az *= di; aw *= di;
            }
            // bf16 hi/lo split, store into MMA-swizzled smem (byte-matches R8 staging)
            float rx, ry, rz, rw;
            uint2 hv, lv;
            hv.x = pack_hi(ax, ay, rx, ry);
            hv.y = pack_hi(az, aw, rz, rw);
            lv.x = pack_lo(rx, ry);
            lv.y = pack_lo(rz, rw);
            uint32_t unit = (uint32_t)((lid >> 3) * 512 + r * 4 +
                                       (((lid >> 1) & 3) ^ ((r >> 1) & 3)));
            ((uint2*)smem4)[unit * 2 + (lid & 1)] = hv;
            ((uint2*)(smem4 + 2048))[unit * 2 + (lid & 1)] = lv;
        }

        // ---- MMA phase: 4 K-chunks, B staged per chunk ----
        float acc[16][4];
        #pragma unroll
        for (int t = 0; t < 16; ++t)
            #pragma unroll
            for (int j2 = 0; j2 < 4; ++j2) acc[t][j2] = 0.f;

        for (int c = 0; c < 4; ++c) {
            #pragma unroll
            for (int f = tid; f < 512; f += 256) {
                int row = f >> 2, ch = f & 3;
                size_t gi = (size_t)row * 16 + c * 4 + ch;
                int du = row * 4 + (ch ^ ((row >> 1) & 3));
                smem4[4096 + du] = Wh[gi];
                smem4[4608 + du] = Wl_[gi];
            }
            __syncthreads();

            #pragma unroll
            for (int ks = 0; ks < 2; ++ks) {
                uint32_t aoff = c * 8192 + a_base + (((ks * 2 + a_half) ^ a_x) << 4);
                uint32_t ah0, ah1, ah2, ah3, al0, al1, al2, al3;
                ldsm_x4(ah0, ah1, ah2, ah3, sA_b + aoff);
                ldsm_x4(al0, al1, al2, al3, sAl_b + aoff);
                #pragma unroll
                for (int jp = 0; jp < 8; ++jp) {
                    uint32_t boff = jp * 1024 + b_base + (((ks * 2 + b_half) ^ b_x) << 4);
                    uint32_t bh0, bh1, bh2, bh3, bl0, bl1, bl2, bl3;
                    ldsm_x4(bh0, bh1, bh2, bh3, sBh_b + boff);
                    mma_bf16(acc[2 * jp],     ah0, ah1, ah2, ah3, bh0, bh1);
                    mma_bf16(acc[2 * jp + 1], ah0, ah1, ah2, ah3, bh2, bh3);
                    mma_bf16(acc[2 * jp],     al0, al1, al2, al3, bh0, bh1);
                    mma_bf16(acc[2 * jp + 1], al0, al1, al2, al3, bh2, bh3);
                    ldsm_x4(bl0, bl1, bl2, bl3, sBl_b + boff);
                    mma_bf16(acc[2 * jp],     ah0, ah1, ah2, ah3, bl0, bl1);
                    mma_bf16(acc[2 * jp + 1], ah0, ah1, ah2, ah3, bl2, bl3);
                }
            }
            __syncthreads();
        }

        // ---- epilogue ----
        int g = lid >> 2, q = lid & 3;
        int r0 = m0 + wid * 16 + g;
        int r1 = r0 + 8;
        float sd0 = (OUT == 0 && r0 < NN) ? g_dinv[r0] : 0.f;
        float sd1 = (OUT == 0 && r1 < NN) ? g_dinv[r1] : 0.f;
        #pragma unroll
        for (int nt = 0; nt < 16; ++nt) {
            int col = nt * 8 + 2 * q;
            float2 bb = *(const float2*)&bias[col];
            float v0 = acc[nt][0] + bb.x, v1 = acc[nt][1] + bb.y;
            float v2 = acc[nt][2] + bb.x, v3 = acc[nt][3] + bb.y;
            v0 = fmaxf(v0, 0.f); v1 = fmaxf(v1, 0.f);
            v2 = fmaxf(v2, 0.f); v3 = fmaxf(v3, 0.f);
            if (OUT == 1) {
                float rx, ry;
                ushort2 hp, lp;
                uint32_t h01 = pack_hi(v0, v1, rx, ry);
                uint32_t l01 = pack_lo(rx, ry);
                hp.x = (unsigned short)(h01 & 0xffff); hp.y = (unsigned short)(h01 >> 16);
                lp.x = (unsigned short)(l01 & 0xffff); lp.y = (unsigned short)(l01 >> 16);
                if (r0 < NN) {
                    *(ushort2*)((__nv_bfloat16*)g_Ah + (size_t)r0 * 128 + col) = hp;
                    *(ushort2*)((__nv_bfloat16*)g_Al + (size_t)r0 * 128 + col) = lp;
                }
                uint32_t h23 = pack_hi(v2, v3, rx, ry);
                uint32_t l23 = pack_lo(rx, ry);
                hp.x = (unsigned short)(h23 & 0xffff); hp.y = (unsigned short)(h23 >> 16);
                lp.x = (unsigned short)(l23 & 0xffff); lp.y = (unsigned short)(l23 >> 16);
                if (r1 < NN) {
                    *(ushort2*)((__nv_bfloat16*)g_Ah + (size_t)r1 * 128 + col) = hp;
                    *(ushort2*)((__nv_bfloat16*)g_Al + (size_t)r1 * 128 + col) = lp;
                }
            } else {
                float* C = (float*)g_bufB;
                if (r0 < NN) *(float2*)&C[(size_t)r0 * 128 + col] = make_float2(v0 * sd0, v1 * sd0);
                if (r1 < NN) *(float2*)&C[(size_t)r1 * 128 + col] = make_float2(v2 * sd1, v3 * sd1);
            }
        }
        __syncthreads();   // protect smem A before next tile's gather
    }
}

// ---------------- head GEMM (verified R8, N=64, reads g_Ah/g_Al) ----------------
__global__ void __launch_bounds__(256) head_gemm(const float* __restrict__ bias,
                                                 float* __restrict__ outp) {
    constexpr int N = 64;
    constexpr int NT = N / 8;
    __shared__ uint4 sAh[128 * 4], sAl[128 * 4];
    __shared__ uint4 sBh[N * 4],   sBl[N * 4];

    int tid = threadIdx.x;
    int wid = tid >> 5;
    int lid = tid & 31;
    int m0  = blockIdx.x * 128;

    float acc[NT][4];
    #pragma unroll
    for (int t = 0; t < NT; ++t)
        #pragma unroll
        for (int j = 0; j < 4; ++j) acc[t][j] = 0.f;

    uint32_t sAh_b = smem_u32(sAh), sAl_b = smem_u32(sAl);
    uint32_t sBh_b = smem_u32(sBh), sBl_b = smem_u32(sBl);

    uint32_t a_row  = lid & 15;
    uint32_t a_half = lid >> 4;
    uint32_t a_x    = (a_row >> 1) & 3;
    uint32_t a_base = (wid * 16 + a_row) * 64;
    uint32_t b_c    = (lid & 7) + ((lid >> 4) & 1) * 8;
    uint32_t b_half = (lid >> 3) & 1;
    uint32_t b_x    = (b_c >> 1) & 3;
    uint32_t b_base = b_c * 64;

    for (int c = 0; c < 4; ++c) {
        #pragma unroll
        for (int f = tid; f < 128 * 4; f += 256) {
            int row = f >> 2, ch = f & 3;
            int gr = m0 + row;
            uint4 vh = make_uint4(0, 0, 0, 0), vl = vh;
            if (gr < NN) {
                size_t gi = (size_t)gr * 16 + c * 4 + ch;
                vh = g_Ah[gi]; vl = g_Al[gi];
            }
            int du = row * 4 + (ch ^ ((row >> 1) & 3));
            sAh[du] = vh; sAl[du] = vl;
        }
        #pragma unroll
        for (int f = tid; f < N * 4; f += 256) {
            int row = f >> 2, ch = f & 3;
            size_t gi = (size_t)row * 16 + c * 4 + ch;
            int du = row * 4 + (ch ^ ((row >> 1) & 3));
            sBh[du] = g_W3h[gi]; sBl[du] = g_W3l[gi];
        }
        __syncthreads();

        #pragma unroll
        for (int ks = 0; ks < 2; ++ks) {
            uint32_t aoff = a_base + (((ks * 2 + a_half) ^ a_x) << 4);
            uint32_t ah0, ah1, ah2, ah3, al0, al1, al2, al3;
            ldsm_x4(ah0, ah1, ah2, ah3, sAh_b + aoff);
            ldsm_x4(al0, al1, al2, al3, sAl_b + aoff);
            #pragma unroll
            for (int jp = 0; jp < NT / 2; ++jp) {
                uint32_t boff = jp * 1024 + b_base + (((ks * 2 + b_half) ^ b_x) << 4);
                uint32_t bh0, bh1, bh2, bh3, bl0, bl1, bl2, bl3;
                ldsm_x4(bh0, bh1, bh2, bh3, sBh_b + boff);
                mma_bf16(acc[2 * jp],     ah0, ah1, ah2, ah3, bh0, bh1);
                mma_bf16(acc[2 * jp + 1], ah0, ah1, ah2, ah3, bh2, bh3);
                mma_bf16(acc[2 * jp],     al0, al1, al2, al3, bh0, bh1);
                mma_bf16(acc[2 * jp + 1], al0, al1, al2, al3, bh2, bh3);
                ldsm_x4(bl0, bl1, bl2, bl3, sBl_b + boff);
                mma_bf16(acc[2 * jp],     ah0, ah1, ah2, ah3, bl0, bl1);
                mma_bf16(acc[2 * jp + 1], ah0, ah1, ah2, ah3, bl2, bl3);
            }
        }
        __syncthreads();
    }

    int g = lid >> 2, q = lid & 3;
    int r0 = m0 + wid * 16 + g;
    int r1 = r0 + 8;
    #pragma unroll
    for (int nt = 0; nt < NT; ++nt) {
        int col = nt * 8 + 2 * q;
        float2 bb = *(const float2*)&bias[col];
        float v0 = acc[nt][0] + bb.x, v1 = acc[nt][1] + bb.y;
        float v2 = acc[nt][2] + bb.x, v3 = acc[nt][3] + bb.y;
        if (r0 < NN) *(float2*)&outp[(size_t)r0 * N + col] = make_float2(v0, v1);
        if (r1 < NN) *(float2*)&outp[(size_t)r1 * N + col] = make_float2(v2, v3);
    }
}

// ---------------- launch ----------------
extern "C" void kernel_launch(void* const* d_in, const int* in_sizes, int n_in,
                              void* d_out, int out_size) {
    const float* x  = (const float*)d_in[0];
    const float* W1 = (const float*)d_in[2];
    const float* b1 = (const float*)d_in[3];
    const float* W2 = (const float*)d_in[4];
    const float* b2 = (const float*)d_in[5];
    const float* Wl = (const float*)d_in[6];
    const float* bl = (const float*)d_in[7];
    float*       out = (float*)d_out;

    const int FSMEM = 5120 * 16;   // 80 KB
    cudaFuncSetAttribute(prop_gemm<false, 0, 1>,
                         cudaFuncAttributeMaxDynamicSharedMemorySize, FSMEM);
    cudaFuncSetAttribute(prop_gemm<true, 1, 2>,
                         cudaFuncAttributeMaxDynamicSharedMemorySize, FSMEM);

    // CSR build + weight split
    zero_cnt_kernel<<<NB, 256>>>();
    edges_kernel<<<(NE / 4 + 255) / 256, 256>>>((const unsigned int*)d_in[1]);
    split_w_kernel<<<160, 256>>>(W1, W2, Wl);
    scan1_kernel<<<NB, 256>>>();
    scan2_kernel<<<1, 64>>>();
    scan3_kernel<<<NB, 256>>>();
    fill_kernel<<<(NE / 4 + 255) / 256, 256>>>();

    // layer 1 fused: prop(x) + GEMM(W1) -> bufB (f32, relu, pre-scaled by dinv)
    prop_gemm<false, 0, 1><<<296, 256, FSMEM>>>(x, b1);
    // layer 2 fused: prop(bufB, scaled) + GEMM(W2) -> Ah/Al (bf16 split, relu)
    prop_gemm<true, 1, 2><<<296, 256, FSMEM>>>(nullptr, b2);
    // head: Ah/Al @ Wl + bl -> out
    head_gemm<<<(NN + 127) / 128, 256>>>(bl, out);
}